// round 9
// baseline (speedup 1.0000x reference)
#include <cuda_runtime.h>

#define FULL 0xFFFFFFFFu

// Problem constants
#define BATCH 32
#define IN    2048
#define OUT   2048
#define KNUM  8
#define HDIM  512
#define KSZ   (IN * OUT)          // 4M elements per expert

#define IBLK   512                // i-range per main block (4 x 128 halves)
#define NCHUNK (IN / IBLK)        // 4
#define OBLK   16                 // o's per block (8 warps x 2 o)
#define NOBLK  (OUT / OBLK)       // 128
#define XSTR   516                // x_s row stride (phase-conflict-free LDS.128)

// Scratch (device globals; returned to initial state every call -> replay safe)
__device__ float    g_h[HDIM];        // zero-init; re-zeroed by last block
__device__ unsigned g_ticket;         // zero-init; reset by last block
__device__ float    g_alpha[KNUM];

// ---------------------------------------------------------------------------
// Fused MLP: 128 blocks x 512 thr. Each block: 16-row partial of cond@w1
// atomically accumulated into g_h, zeroes its slice of out. Last block
// (threadfence ticket) does relu -> @w2 + b2 -> softmax -> g_alpha, then
// resets g_h and g_ticket for the next graph replay.
// ---------------------------------------------------------------------------
__global__ void mlp_kernel(const float* __restrict__ cond,
                           const float* __restrict__ w1,
                           const float* __restrict__ b1,
                           const float* __restrict__ w2,
                           const float* __restrict__ b2,
                           float* __restrict__ out) {
    __shared__ float    h_s[HDIM];
    __shared__ float    s_s[KNUM];
    __shared__ unsigned rank_s;

    int j  = threadIdx.x;         // 0..511
    int p  = blockIdx.x;          // 0..127
    int i0 = p * 16;

    float s[8];
#pragma unroll
    for (int u = 0; u < 8; ++u)
        s[u] = cond[i0 + u] * w1[(i0 + u) * HDIM + j];
#pragma unroll
    for (int u = 0; u < 8; ++u)
        s[u] += cond[i0 + 8 + u] * w1[(i0 + 8 + u) * HDIM + j];
    float sum = ((s[0] + s[1]) + (s[2] + s[3])) + ((s[4] + s[5]) + (s[6] + s[7]));

    atomicAdd(&g_h[j], sum);
    out[p * HDIM + j] = 0.f;      // zero out for main's atomic accumulation

    __threadfence();
    __syncthreads();
    if (j == 0) rank_s = atomicAdd(&g_ticket, 1u);
    __syncthreads();
    if (rank_s != gridDim.x - 1) return;

    // ---- last block: finish the MLP ----
    __threadfence();
    h_s[j] = fmaxf(g_h[j] + b1[j], 0.f);
    __syncthreads();

    int wid = j >> 5, lane = j & 31;
    if (wid < KNUM) {
        float sc = 0.f;
#pragma unroll
        for (int m = 0; m < HDIM / 32; ++m) {
            int jj = lane + m * 32;
            sc += h_s[jj] * w2[jj * KNUM + wid];
        }
#pragma unroll
        for (int off = 16; off; off >>= 1) sc += __shfl_xor_sync(FULL, sc, off);
        if (lane == 0) s_s[wid] = sc + b2[wid];
    }
    __syncthreads();
    if (j == 0) {
        float mx = -1e30f;
#pragma unroll
        for (int k = 0; k < KNUM; ++k) mx = fmaxf(mx, s_s[k]);
        float e[KNUM];
        float ssum = 0.f;
#pragma unroll
        for (int k = 0; k < KNUM; ++k) { e[k] = __expf(s_s[k] - mx); ssum += e[k]; }
        float inv = 1.f / ssum;
#pragma unroll
        for (int k = 0; k < KNUM; ++k) g_alpha[k] = e[k] * inv;
        g_ticket = 0;             // reset for next call
    }
    g_h[j] = 0.f;                 // reset for next call
}

// ---------------------------------------------------------------------------
// Main: out[b,o] (+)= sum_{i in chunk} (sum_k a_k KW[k,o,i]) * x[b,i]
// grid = 512 blocks x 256 threads (8 warps x 2 o), 3 blocks/SM (24 warps).
// Register-lean pipeline: only the 4-expert A-group is prefetched across
// halves (32 regs); the B-group is loaded at each half and its latency is
// absorbed by the other 23 warps. lane = batch row b.
// ---------------------------------------------------------------------------
__global__ __launch_bounds__(256, 3) void main_kernel(
        const float* __restrict__ x,    // [32, 2048]
        const float* __restrict__ kw,   // [8, 2048, 2048]
        const float* __restrict__ kb,   // [8, 2048]
        float* __restrict__ out) {      // [32, 2048]
    extern __shared__ float sm[];
    float* x_s   = sm;                            // 32 * 516 = 16512 floats
    float* w_s   = sm + BATCH * XSTR;             // 8 warps * 2 * 128 = 2048
    float* out_s = w_s;                           // aliased (used after sync)
    float* a_s   = w_s + 8 * 2 * 128;             // 8

    int t    = threadIdx.x;
    int wid  = t >> 5;
    int lane = t & 31;
    int ob   = blockIdx.x & (NOBLK - 1);          // 0..127
    int c    = blockIdx.x >> 7;                   // 0..3
    int i0   = c * IBLK;
    int o0   = ob * OBLK + wid;                   // warp's o pair: o0, o0+8

    if (t < KNUM) a_s[t] = g_alpha[t];

    const float* base0 = kw + (size_t)o0 * IN + i0 + lane * 4;
    const float* base1 = base0 + 8 * IN;          // o1 = o0 + 8

    // preload A-group (k=0..3) of half 0 BEFORE x staging
    float4 c0[4], c1[4];
#pragma unroll
    for (int k = 0; k < 4; ++k) {
        c0[k] = *reinterpret_cast<const float4*>(base0 + (size_t)k * KSZ);
        c1[k] = *reinterpret_cast<const float4*>(base1 + (size_t)k * KSZ);
    }

    // stage x tile: x_s[b][il] = x[b][i0+il], float4 (full 512-i tile)
    const float4* x4 = reinterpret_cast<const float4*>(x);
#pragma unroll
    for (int jj = 0; jj < (BATCH * IBLK) / (4 * 256); ++jj) {
        int idx = jj * 256 + t;                   // 0..4095 float4 units
        int b   = idx >> 7;                       // 128 f4 per row
        int il4 = idx & 127;
        *reinterpret_cast<float4*>(&x_s[b * XSTR + il4 * 4]) =
            x4[(b * IN + i0) / 4 + il4];
    }
    __syncthreads();

    float4 acc0 = make_float4(0.f, 0.f, 0.f, 0.f);
    float4 acc1 = make_float4(0.f, 0.f, 0.f, 0.f);

#pragma unroll
    for (int h = 0; h < IBLK / 128; ++h) {
        int off = h * 128;

        // ---- partial aggregation from A-group (frees c0/c1) ----
        float4 w40 = make_float4(0.f, 0.f, 0.f, 0.f);
        float4 w41 = make_float4(0.f, 0.f, 0.f, 0.f);
#pragma unroll
        for (int k = 0; k < 4; ++k) {
            float ak = a_s[k];
            w40.x += ak * c0[k].x; w40.y += ak * c0[k].y;
            w40.z += ak * c0[k].z; w40.w += ak * c0[k].w;
            w41.x += ak * c1[k].x; w41.y += ak * c1[k].y;
            w41.z += ak * c1[k].z; w41.w += ak * c1[k].w;
        }

        // ---- load B-group (k=4..7) of this half into the same regs ----
        // (stall here is absorbed by the other warps on this SM)
#pragma unroll
        for (int k = 0; k < 4; ++k) {
            c0[k] = *reinterpret_cast<const float4*>(
                        base0 + (size_t)(k + 4) * KSZ + off);
            c1[k] = *reinterpret_cast<const float4*>(
                        base1 + (size_t)(k + 4) * KSZ + off);
        }
#pragma unroll
        for (int k = 0; k < 4; ++k) {
            float ak = a_s[k + 4];
            w40.x += ak * c0[k].x; w40.y += ak * c0[k].y;
            w40.z += ak * c0[k].z; w40.w += ak * c0[k].w;
            w41.x += ak * c1[k].x; w41.y += ak * c1[k].y;
            w41.z += ak * c1[k].z; w41.w += ak * c1[k].w;
        }

        // ---- prefetch A-group of next half (hidden under compute) ----
        if (h < IBLK / 128 - 1) {
#pragma unroll
            for (int k = 0; k < 4; ++k) {
                c0[k] = *reinterpret_cast<const float4*>(
                            base0 + (size_t)k * KSZ + off + 128);
                c1[k] = *reinterpret_cast<const float4*>(
                            base1 + (size_t)k * KSZ + off + 128);
            }
        }

        // ---- stage aggregated strips (warp-private rows) ----
        *reinterpret_cast<float4*>(&w_s[(wid * 2 + 0) * 128 + lane * 4]) = w40;
        *reinterpret_cast<float4*>(&w_s[(wid * 2 + 1) * 128 + lane * 4]) = w41;
        __syncwarp();

        // ---- compute: lane = b; 4 i per iter ----
#pragma unroll
        for (int src = 0; src < 32; ++src) {
            float4 xq  = *reinterpret_cast<const float4*>(
                             &x_s[lane * XSTR + off + src * 4]);
            float4 wq0 = *reinterpret_cast<const float4*>(
                             &w_s[(wid * 2 + 0) * 128 + src * 4]);
            float4 wq1 = *reinterpret_cast<const float4*>(
                             &w_s[(wid * 2 + 1) * 128 + src * 4]);
            acc0.x += wq0.x * xq.x; acc0.y += wq0.y * xq.y;
            acc0.z += wq0.z * xq.z; acc0.w += wq0.w * xq.w;
            acc1.x += wq1.x * xq.x; acc1.y += wq1.y * xq.y;
            acc1.z += wq1.z * xq.z; acc1.w += wq1.w * xq.w;
        }
        __syncwarp();   // before w_s overwrite next half
    }

    // ---- epilogue: bias (c==0 only), transpose via w_s alias, atomic add ----
    float bb0 = 0.f, bb1 = 0.f;
    if (c == 0) {
#pragma unroll
        for (int k = 0; k < KNUM; ++k) {
            bb0 += a_s[k] * kb[k * OUT + o0];
            bb1 += a_s[k] * kb[k * OUT + o0 + 8];
        }
    }
    float v0 = (acc0.x + acc0.y) + (acc0.z + acc0.w) + bb0;
    float v1 = (acc1.x + acc1.y) + (acc1.z + acc1.w) + bb1;

    __syncthreads();                 // all warps done reading w_s
    out_s[lane * 17 + wid]     = v0; // lane = b
    out_s[lane * 17 + wid + 8] = v1;
    __syncthreads();
#pragma unroll
    for (int r = 0; r < 2; ++r) {
        int idx = r * 256 + t;                    // 0..511
        int b   = idx >> 4;
        int oi  = idx & 15;
        atomicAdd(&out[b * OUT + ob * OBLK + oi], out_s[b * 17 + oi]);
    }
}

// ---------------------------------------------------------------------------
extern "C" void kernel_launch(void* const* d_in, const int* in_sizes, int n_in,
                              void* d_out, int out_size) {
    const float* x    = (const float*)d_in[0];
    const float* cond = (const float*)d_in[1];
    const float* w1   = (const float*)d_in[2];
    const float* b1   = (const float*)d_in[3];
    const float* w2   = (const float*)d_in[4];
    const float* b2   = (const float*)d_in[5];
    const float* kw   = (const float*)d_in[6];
    const float* kb   = (const float*)d_in[7];
    float* out = (float*)d_out;

    const int SMEM_MAIN = (BATCH * XSTR + 8 * 2 * 128 + 8) * 4;  // 74272 B
    static int smem_set = 0;
    if (!smem_set) {
        cudaFuncSetAttribute(main_kernel,
                             cudaFuncAttributeMaxDynamicSharedMemorySize,
                             SMEM_MAIN);
        smem_set = 1;
    }

    mlp_kernel<<<128, HDIM>>>(cond, w1, b1, w2, b2, out);
    main_kernel<<<NCHUNK * NOBLK, 256, SMEM_MAIN>>>(x, kw, kb, out);
}